// round 4
// baseline (speedup 1.0000x reference)
#include <cuda_runtime.h>

#define WPB 4                      // warps (molecules) per block
#define MAXB4 2048                 // 8192 floats capacity
__device__ float4 g_partial4[MAXB4];
__device__ unsigned int g_count = 0;   // last block resets -> deterministic across graph replays

__device__ __forceinline__ float fast_sqrt(float x) {
    float y;
    asm("sqrt.approx.f32 %0, %1;" : "=f"(y) : "f"(x));
    return y;
}

// One WARP per molecule, 4 molecules per 128-thread CTA.
__global__ void __launch_bounds__(32 * WPB) mol_kernel(
    const float* __restrict__ coords,     // [N,3]
    const int*   __restrict__ species,    // [N]
    const int*   __restrict__ bidx,       // [N] sorted ascending
    const int*   __restrict__ natoms,     // [B]
    const float* __restrict__ radii,      // [95]
    float*       __restrict__ out,        // [1 + 3N]
    int B, int N, int nblocks)
{
    const int tid  = threadIdx.x;
    const int wid  = tid >> 5;
    const int lane = tid & 31;
    const int m    = blockIdx.x * WPB + wid;    // molecule id

    __shared__ float4   s4[WPB][64];
    __shared__ float    s_red[WPB];
    __shared__ unsigned s_ticket;

    float* g_partial = (float*)g_partial4;

    if (m < B) {
        const int n = natoms[m];

        // ---- offset: analytic guess (sizes are 8 + m%57), verified; fallback ballot search ----
        int off;
        {
            const int q = m / 57, r = m - q * 57;
            int guess = 8 * m + q * 1596 + ((r * (r - 1)) >> 1);
            guess = max(0, min(guess, N));
            int okv = 0;
            if (lane == 0) {
                const int lo = (guess > 0) ? bidx[guess - 1] : -1;
                const int hi = (guess < N) ? bidx[guess] : 0x7fffffff;
                okv = (lo < m) && (hi >= m);
            }
            okv = __shfl_sync(0xffffffffu, okv, 0);
            if (okv) {
                off = guess;
            } else {
                int lo = 0, hi = N;
                while (hi - lo > 32) {
                    const int step = ((hi - lo) + 31) >> 5;
                    const int qq = lo + (lane + 1) * step;
                    const unsigned mm = __ballot_sync(0xffffffffu, (qq < hi) && (bidx[qq] < m));
                    lo += __popc(mm) * step;
                    const int nh = lo + step;
                    hi = nh < hi ? nh : hi;
                }
                const unsigned mm = __ballot_sync(0xffffffffu, (lo + lane < hi) && (bidx[lo + lane] < m));
                off = lo + __popc(mm);
            }
        }
        const int base = 3 * off;

        // ---- load 2 atoms per lane ----
        const int a0 = lane, a1 = lane + 32;
        const bool act0 = a0 < n, act1 = a1 < n;
        float x0 = 0.f, y0 = 0.f, z0 = 0.f, r0 = 0.f;
        float x1 = 0.f, y1 = 0.f, z1 = 0.f, r1 = 0.f;
        if (act0) {
            const int g = base + 3 * a0;
            x0 = coords[g]; y0 = coords[g + 1]; z0 = coords[g + 2];
            r0 = 0.8f * radii[species[off + a0]];
        }
        if (act1) {
            const int g = base + 3 * a1;
            x1 = coords[g]; y1 = coords[g + 1]; z1 = coords[g + 2];
            r1 = 0.8f * radii[species[off + a1]];
        }
        s4[wid][a0] = make_float4(x0, y0, z0, r0);
        s4[wid][a1] = make_float4(x1, y1, z1, r1);
        __syncwarp();

        // ---- symmetric round-robin over 64 virtual rows: each unordered pair once ----
        float pen = 0.f;
        if (act0) {
            const int F = (n - 1) >> 1;
            int j0 = a0;
            int j1 = act1 ? a1 : 0;
            for (int k = 1; k <= F; ++k) {
                ++j0; j0 = (j0 == n) ? 0 : j0;
                ++j1; j1 = (j1 == n) ? 0 : j1;
                {
                    const float4 o = s4[wid][j0];
                    const float dx = x0 - o.x, dy = y0 - o.y, dz = z0 - o.z;
                    const float d2 = fmaf(dx, dx, fmaf(dy, dy, fmaf(dz, dz, 1e-8f)));
                    float t = (r0 + o.w) - fast_sqrt(d2);
                    t = fmaxf(t, 0.f);
                    pen = fmaf(t, t, pen);
                }
                if (act1) {
                    const float4 o = s4[wid][j1];
                    const float dx = x1 - o.x, dy = y1 - o.y, dz = z1 - o.z;
                    const float d2 = fmaf(dx, dx, fmaf(dy, dy, fmaf(dz, dz, 1e-8f)));
                    float t = (r1 + o.w) - fast_sqrt(d2);
                    t = fmaxf(t, 0.f);
                    pen = fmaf(t, t, pen);
                }
            }
            if (!(n & 1) && a0 < (n >> 1)) {     // half column (only v<32 can qualify: n<=64)
                const float4 o = s4[wid][a0 + (n >> 1)];
                const float dx = x0 - o.x, dy = y0 - o.y, dz = z0 - o.z;
                const float d2 = fmaf(dx, dx, fmaf(dy, dy, fmaf(dz, dz, 1e-8f)));
                float t = (r0 + o.w) - fast_sqrt(d2);
                t = fmaxf(t, 0.f);
                pen = fmaf(t, t, pen);
            }
        }

        // ---- warp butterfly reduce: pen + coord sums (all lanes get result) ----
        float sx = x0 + x1, sy = y0 + y1, sz = z0 + z1;
#pragma unroll
        for (int s = 16; s > 0; s >>= 1) {
            pen += __shfl_xor_sync(0xffffffffu, pen, s);
            sx  += __shfl_xor_sync(0xffffffffu, sx,  s);
            sy  += __shfl_xor_sync(0xffffffffu, sy,  s);
            sz  += __shfl_xor_sync(0xffffffffu, sz,  s);
        }
        const float inv = 1.f / (float)n;
        const float mx = sx * inv, my = sy * inv, mz = sz * inv;

        if (lane == 0) {
            g_partial[m] = pen * (2.f * inv);   // x2: symmetric pairs
            __threadfence();
        }

        // ---- centered coords ----
        if (act0) {
            const int g = base + 3 * a0;
            out[1 + g]     = x0 - mx;
            out[1 + g + 1] = y0 - my;
            out[1 + g + 2] = z0 - mz;
        }
        if (act1) {
            const int g = base + 3 * a1;
            out[1 + g]     = x1 - mx;
            out[1 + g + 1] = y1 - my;
            out[1 + g + 2] = z1 - mz;
        }
    }

    // ---- fused final reduction: last block sums g_partial -> out[0] ----
    __syncthreads();
    if (tid == 0) s_ticket = atomicAdd(&g_count, 1u);
    __syncthreads();
    if (s_ticket == (unsigned)(nblocks - 1)) {
        __threadfence();
        float a0 = 0.f, a1 = 0.f, a2 = 0.f, a3 = 0.f;
        const int nf4 = B >> 2;
        for (int i = tid; i < nf4; i += 32 * WPB) {
            const float4 v = __ldcg(&g_partial4[i]);
            a0 += v.x; a1 += v.y; a2 += v.z; a3 += v.w;
        }
        float v = (a0 + a1) + (a2 + a3);
        for (int i = (nf4 << 2) + tid; i < B; i += 32 * WPB) v += __ldcg(&g_partial[i]);
#pragma unroll
        for (int s = 16; s > 0; s >>= 1) v += __shfl_xor_sync(0xffffffffu, v, s);
        if (lane == 0) s_red[wid] = v;
        __syncthreads();
        if (tid == 0) {
            float t = 0.f;
#pragma unroll
            for (int w = 0; w < WPB; ++w) t += s_red[w];
            out[0] = t / (float)B;
            g_count = 0;                       // reset for next graph replay
        }
    }
}

extern "C" void kernel_launch(void* const* d_in, const int* in_sizes, int n_in,
                              void* d_out, int out_size)
{
    const float* coords  = (const float*)d_in[0];  // [N,3]
    const int*   species = (const int*)  d_in[1];  // [N]
    const int*   bidx    = (const int*)  d_in[2];  // [N]
    const int*   natoms  = (const int*)  d_in[3];  // [B]
    const float* radii   = (const float*)d_in[4];  // [95]
    float* out = (float*)d_out;

    const int N = in_sizes[0] / 3;
    const int B = in_sizes[3];
    const int nblocks = (B + WPB - 1) / WPB;

    mol_kernel<<<nblocks, 32 * WPB>>>(coords, species, bidx, natoms, radii, out, B, N, nblocks);
}

// round 6
// speedup vs baseline: 1.1746x; 1.1746x over previous
#include <cuda_runtime.h>

#define WPB 4                      // warps (molecules) per block
#define MAXB4 2048                 // 8192 floats capacity
__device__ float4 g_partial4[MAXB4];
__device__ unsigned int g_count = 0;   // last block resets -> deterministic across graph replays

__device__ __forceinline__ float fast_sqrt(float x) {
    float y;
    asm("sqrt.approx.f32 %0, %1;" : "=f"(y) : "f"(x));
    return y;
}

// Warp-cooperative lower_bound(bidx, m) over sorted bidx[0..N)
__device__ __forceinline__ int warp_lower_bound(const int* __restrict__ bidx,
                                                int N, int m, int lane) {
    int lo = 0, hi = N;
    while (hi - lo > 32) {
        const int step = ((hi - lo) + 31) >> 5;
        const int q = lo + (lane + 1) * step;
        const unsigned mm = __ballot_sync(0xffffffffu, (q < hi) && (bidx[q] < m));
        lo += __popc(mm) * step;
        const int nh = lo + step;
        hi = nh < hi ? nh : hi;
    }
    const unsigned mm = __ballot_sync(0xffffffffu, (lo + lane < hi) && (bidx[lo + lane] < m));
    return lo + __popc(mm);
}

// One WARP per molecule, 4 molecules per 128-thread CTA.
__global__ void __launch_bounds__(32 * WPB) mol_kernel(
    const float* __restrict__ coords,     // [N,3]
    const int*   __restrict__ species,    // [N]
    const int*   __restrict__ bidx,       // [N] sorted ascending
    const int*   __restrict__ natoms,     // [B]
    const float* __restrict__ radii,      // [95]
    float*       __restrict__ out,        // [1 + 3N]
    int B, int N, int nblocks)
{
    const int tid  = threadIdx.x;
    const int wid  = tid >> 5;
    const int lane = tid & 31;
    const int m    = blockIdx.x * WPB + wid;    // molecule id

    __shared__ float4   s4[WPB][128];           // doubled buffer: atom i at [i] and [i+n]
    __shared__ float    s_red[WPB];
    __shared__ unsigned s_ticket;

    float* g_partial = (float*)g_partial4;

    if (m < B) {
        const int n = natoms[m];

        // ---- analytic offset guess (sizes are 8 + m%57), verified lazily ----
        const int q = m / 57, r = m - q * 57;
        int off = 8 * m + q * 1596 + ((r * (r - 1)) >> 1);
        off = max(0, min(off, N - n));           // always in-bounds for speculative loads

        // verify loads (lane 0) — overlap with speculative coord loads below
        int lov = -1, hiv = 0x7fffffff;
        if (lane == 0) {
            if (off > 0) lov = bidx[off - 1];
            if (off < N) hiv = bidx[off];
        }

        const int a0 = lane, a1 = lane + 32;
        const bool act0 = a0 < n;
        const bool act1 = a1 < n;

        // speculative loads at guessed offset
        int base = 3 * off;
        float x0, y0, z0, r0;
        float x1 = 0.f, y1 = 0.f, z1 = 0.f, r1 = 0.f;
        {
            const int g = base + 3 * a0;
            x0 = coords[g]; y0 = coords[g + 1]; z0 = coords[g + 2];
            r0 = 0.8f * radii[species[off + a0]];
        }
        if (act1) {
            const int g = base + 3 * a1;
            x1 = coords[g]; y1 = coords[g + 1]; z1 = coords[g + 2];
            r1 = 0.8f * radii[species[off + a1]];
        }

        int okv = (lane == 0) ? ((lov < m) && (hiv >= m)) : 0;
        okv = __shfl_sync(0xffffffffu, okv, 0);
        if (!okv) {                               // cold path: full search + reload
            off  = warp_lower_bound(bidx, N, m, lane);
            base = 3 * off;
            const int g = base + 3 * a0;
            x0 = coords[g]; y0 = coords[g + 1]; z0 = coords[g + 2];
            r0 = 0.8f * radii[species[off + a0]];
            if (act1) {
                const int g1 = base + 3 * a1;
                x1 = coords[g1]; y1 = coords[g1 + 1]; z1 = coords[g1 + 2];
                r1 = 0.8f * radii[species[off + a1]];
            }
        }

        if (!act0) { x0 = y0 = z0 = r0 = 0.f; }   // zero inactive rows (mean sums rely on this)

        // ---- fill doubled shared buffer ----
        const float4 v0 = make_float4(x0, y0, z0, r0);
        s4[wid][a0] = v0;
        if (act0) s4[wid][a0 + n] = v0;
        if (act1) {
            const float4 v1 = make_float4(x1, y1, z1, r1);
            s4[wid][a1]     = v1;
            s4[wid][a1 + n] = v1;
        }
        __syncwarp();

        // ---- symmetric round-robin, no wrap: partner of row a is s4[a + k] ----
        float pen = 0.f;
        const int F = (n - 1) >> 1;
        const float4* p = &s4[wid][lane];
        if (act1) {
#pragma unroll 4
            for (int k = 1; k <= F; ++k) {
                {
                    const float4 o = p[k];
                    const float dx = x0 - o.x, dy = y0 - o.y, dz = z0 - o.z;
                    const float d2 = fmaf(dx, dx, fmaf(dy, dy, fmaf(dz, dz, 1e-8f)));
                    float t = fmaxf((r0 + o.w) - fast_sqrt(d2), 0.f);
                    pen = fmaf(t, t, pen);
                }
                {
                    const float4 o = p[k + 32];
                    const float dx = x1 - o.x, dy = y1 - o.y, dz = z1 - o.z;
                    const float d2 = fmaf(dx, dx, fmaf(dy, dy, fmaf(dz, dz, 1e-8f)));
                    float t = fmaxf((r1 + o.w) - fast_sqrt(d2), 0.f);
                    pen = fmaf(t, t, pen);
                }
            }
        } else {
#pragma unroll 4
            for (int k = 1; k <= F; ++k) {
                const float4 o = p[k];
                const float dx = x0 - o.x, dy = y0 - o.y, dz = z0 - o.z;
                const float d2 = fmaf(dx, dx, fmaf(dy, dy, fmaf(dz, dz, 1e-8f)));
                float t = fmaxf((r0 + o.w) - fast_sqrt(d2), 0.f);
                pen = fmaf(t, t, pen);
            }
        }
        if (!act0) pen = 0.f;                     // inactive lanes (n<=31) read garbage; discard

        if (!(n & 1) && a0 < (n >> 1)) {          // half column for even n
            const float4 o = p[n >> 1];
            const float dx = x0 - o.x, dy = y0 - o.y, dz = z0 - o.z;
            const float d2 = fmaf(dx, dx, fmaf(dy, dy, fmaf(dz, dz, 1e-8f)));
            float t = fmaxf((r0 + o.w) - fast_sqrt(d2), 0.f);
            pen = fmaf(t, t, pen);
        }

        // ---- warp butterfly reduce: pen + coord sums (all lanes get result) ----
        float sx = x0 + x1, sy = y0 + y1, sz = z0 + z1;
#pragma unroll
        for (int s = 16; s > 0; s >>= 1) {
            pen += __shfl_xor_sync(0xffffffffu, pen, s);
            sx  += __shfl_xor_sync(0xffffffffu, sx,  s);
            sy  += __shfl_xor_sync(0xffffffffu, sy,  s);
            sz  += __shfl_xor_sync(0xffffffffu, sz,  s);
        }
        const float inv = 1.f / (float)n;
        const float mx = sx * inv, my = sy * inv, mz = sz * inv;

        if (lane == 0) {
            g_partial[m] = pen * (2.f * inv);     // x2: symmetric pairs
            __threadfence();
        }

        // ---- centered coords ----
        if (act0) {
            const int g = base + 3 * a0;
            out[1 + g]     = x0 - mx;
            out[1 + g + 1] = y0 - my;
            out[1 + g + 2] = z0 - mz;
        }
        if (act1) {
            const int g = base + 3 * a1;
            out[1 + g]     = x1 - mx;
            out[1 + g + 1] = y1 - my;
            out[1 + g + 2] = z1 - mz;
        }
    }

    // ---- fused final reduction: last block sums g_partial -> out[0] ----
    __syncthreads();
    if (tid == 0) s_ticket = atomicAdd(&g_count, 1u);
    __syncthreads();
    if (s_ticket == (unsigned)(nblocks - 1)) {
        __threadfence();
        float a0 = 0.f, a1 = 0.f, a2 = 0.f, a3 = 0.f;
        const int nf4 = B >> 2;
        for (int i = tid; i < nf4; i += 32 * WPB) {
            const float4 v = __ldcg(&g_partial4[i]);
            a0 += v.x; a1 += v.y; a2 += v.z; a3 += v.w;
        }
        float v = (a0 + a1) + (a2 + a3);
        for (int i = (nf4 << 2) + tid; i < B; i += 32 * WPB) v += __ldcg(&((float*)g_partial4)[i]);
#pragma unroll
        for (int s = 16; s > 0; s >>= 1) v += __shfl_xor_sync(0xffffffffu, v, s);
        if (lane == 0) s_red[wid] = v;
        __syncthreads();
        if (tid == 0) {
            float t = 0.f;
#pragma unroll
            for (int w = 0; w < WPB; ++w) t += s_red[w];
            out[0] = t / (float)B;
            g_count = 0;                          // reset for next graph replay
        }
    }
}

extern "C" void kernel_launch(void* const* d_in, const int* in_sizes, int n_in,
                              void* d_out, int out_size)
{
    const float* coords  = (const float*)d_in[0];  // [N,3]
    const int*   species = (const int*)  d_in[1];  // [N]
    const int*   bidx    = (const int*)  d_in[2];  // [N]
    const int*   natoms  = (const int*)  d_in[3];  // [B]
    const float* radii   = (const float*)d_in[4];  // [95]
    float* out = (float*)d_out;

    const int N = in_sizes[0] / 3;
    const int B = in_sizes[3];
    const int nblocks = (B + WPB - 1) / WPB;

    mol_kernel<<<nblocks, 32 * WPB>>>(coords, species, bidx, natoms, radii, out, B, N, nblocks);
}